// round 8
// baseline (speedup 1.0000x reference)
#include <cuda_runtime.h>
#include <cuda_bf16.h>
#include <stdint.h>

#define NB   4
#define SS   4096
#define DD   1024
#define AA   1024
#define NTOK (NB * SS)
#define K3P  (3 * DD)
#define K3S  (3 * SS)

// Scratch (device globals: allocation-free rule)
__device__ float g_Q[(size_t)NTOK * AA];
__device__ float g_K[(size_t)NTOK * AA];
__device__ float g_V[(size_t)NTOK * AA];
__device__ float g_P[(size_t)NB * SS * SS];
__device__ float g_C[(size_t)NTOK * AA];
__device__ __nv_bfloat16 g_xA[(size_t)NTOK * K3P];
__device__ __nv_bfloat16 g_QA[(size_t)NTOK * K3P];
__device__ __nv_bfloat16 g_KB[(size_t)NTOK * K3P];
__device__ __nv_bfloat16 g_CA[(size_t)NTOK * K3P];
__device__ __nv_bfloat16 g_PA[(size_t)NTOK * (size_t)K3S];
__device__ __nv_bfloat16 g_VT[(size_t)NB * AA * (size_t)K3S];
__device__ __nv_bfloat16 g_WqB[(size_t)AA * K3P];
__device__ __nv_bfloat16 g_WkB[(size_t)AA * K3P];
__device__ __nv_bfloat16 g_WvB[(size_t)AA * K3P];
__device__ __nv_bfloat16 g_WoB[(size_t)DD * K3P];

// ---------------- PTX helpers (sm_103-baseline only: no tcgen05/TMA) -------
__device__ __forceinline__ uint32_t smem_u32(const void* p) {
    uint32_t a;
    asm("{ .reg .u64 t; cvta.to.shared.u64 t, %1; cvt.u32.u64 %0, t; }" : "=r"(a) : "l"(p));
    return a;
}
__device__ __forceinline__ void cp16(uint32_t dst, const void* src) {
    asm volatile("cp.async.cg.shared.global [%0], [%1], 16;" :: "r"(dst), "l"(src));
}
#define CP_COMMIT() asm volatile("cp.async.commit_group;" ::: "memory")
#define CP_WAIT2()  asm volatile("cp.async.wait_group 2;" ::: "memory")

#define LDSM4(R0, R1, R2, R3, ADDR) \
    asm volatile("ldmatrix.sync.aligned.m8n8.x4.shared.b16 {%0,%1,%2,%3}, [%4];" \
                 : "=r"(R0), "=r"(R1), "=r"(R2), "=r"(R3) : "r"(ADDR))

__device__ __forceinline__ void mma16816(float* d, const uint32_t* a, const uint32_t* b) {
    asm volatile(
        "mma.sync.aligned.m16n8k16.row.col.f32.bf16.bf16.f32 "
        "{%0,%1,%2,%3}, {%4,%5,%6,%7}, {%8,%9}, {%0,%1,%2,%3};"
        : "+f"(d[0]), "+f"(d[1]), "+f"(d[2]), "+f"(d[3])
        : "r"(a[0]), "r"(a[1]), "r"(a[2]), "r"(a[3]), "r"(b[0]), "r"(b[1]));
}

// ---------------------------------------------------------------------------
// GEMM: out[M,N] fp32 = alpha * A''[M,K3](bf16) * B''[N,K3](bf16)^T + bias
// BM=BN=128, BK=32, 8 warps (2x4), warp tile 64x32, 3-stage cp.async.
// SMEM tile: rows of 64B (32 bf16), 16B chunks swizzled: phys_c = c ^ ((row>>1)&3)
// ---------------------------------------------------------------------------
#define BK 32
#define STG_BYTES 16384            // A 8KB + B 8KB
#define GEMM_SMEM (3 * STG_BYTES)  // 49152

__global__ void __launch_bounds__(256, 1) mma_gemm_kernel(
    const __nv_bfloat16* __restrict__ A, const __nv_bfloat16* __restrict__ B,
    const float* __restrict__ bias, float* __restrict__ out,
    int N, int K3, float alpha, int rowsA, int rowsB)
{
    extern __shared__ __align__(128) char smem[];
    const uint32_t sb = smem_u32(smem);
    const int tid  = threadIdx.x;
    const int lane = tid & 31;
    const int wid  = tid >> 5;
    const int wm   = wid >> 2;       // 0..1
    const int wn   = wid & 3;        // 0..3

    const int aRow = blockIdx.z * rowsA + blockIdx.y * 128;
    const int bRow = blockIdx.z * rowsB + blockIdx.x * 128;

    // cp.async loader assignment: 2 A-chunks + 2 B-chunks of 16B per thread
    const int lr0 = tid >> 2;            // 0..63
    const int lr1 = lr0 + 64;            // 64..127
    const int lc  = tid & 3;             // 16B chunk
    const int sw0 = (lr0 >> 1) & 3;      // swizzle (same for lr0 and lr1)
    const uint32_t dA0 = (uint32_t)(lr0 * 64 + ((lc ^ sw0) * 16));
    const uint32_t dA1 = (uint32_t)(lr1 * 64 + ((lc ^ sw0) * 16));
    const __nv_bfloat16* gA0 = A + (long)(aRow + lr0) * K3 + lc * 8;
    const __nv_bfloat16* gA1 = A + (long)(aRow + lr1) * K3 + lc * 8;
    const __nv_bfloat16* gB0 = B + (long)(bRow + lr0) * K3 + lc * 8;
    const __nv_bfloat16* gB1 = B + (long)(bRow + lr1) * K3 + lc * 8;

    // ldmatrix lane addressing
    const int rA  = wm * 64 + (lane & 15);          // A fragment row (+mf*16)
    const int khA = lane >> 4;                      // A k-half
    const int swA = (rA >> 1) & 3;
    const int rB  = wn * 32 + (lane & 7) + ((lane >> 4) << 3);  // B row (+nfp*16)
    const int khB = (lane >> 3) & 1;
    const int swB = (rB >> 1) & 3;

    float acc[4][4][4];
    #pragma unroll
    for (int i = 0; i < 4; ++i)
        #pragma unroll
        for (int j = 0; j < 4; ++j)
            #pragma unroll
            for (int e = 0; e < 4; ++e) acc[i][j][e] = 0.0f;

    const int NT = K3 / BK;

    // prologue: stages 0,1
    #pragma unroll
    for (int s = 0; s < 2; ++s) {
        const uint32_t ab = sb + s * STG_BYTES;
        const long go = (long)s * BK;
        cp16(ab + dA0,        gA0 + go);
        cp16(ab + dA1,        gA1 + go);
        cp16(ab + 8192 + dA0, gB0 + go);
        cp16(ab + 8192 + dA1, gB1 + go);
        CP_COMMIT();
    }

    for (int kt = 0; kt < NT; ++kt) {
        __syncthreads();   // everyone done reading buffer (kt+2)%3 from iter kt-1
        if (kt + 2 < NT) {
            const int s = (kt + 2) % 3;
            const uint32_t ab = sb + s * STG_BYTES;
            const long go = (long)(kt + 2) * BK;
            cp16(ab + dA0,        gA0 + go);
            cp16(ab + dA1,        gA1 + go);
            cp16(ab + 8192 + dA0, gB0 + go);
            cp16(ab + 8192 + dA1, gB1 + go);
        }
        CP_COMMIT();
        CP_WAIT2();
        __syncthreads();   // group kt data visible to all threads

        const uint32_t ab = sb + (kt % 3) * STG_BYTES;
        const uint32_t bb = ab + 8192;

        #pragma unroll
        for (int ks = 0; ks < 2; ++ks) {
            uint32_t a[4][4], b[4][2];
            #pragma unroll
            for (int mf = 0; mf < 4; ++mf) {
                const uint32_t ad = ab + (uint32_t)((rA + mf * 16) * 64 +
                                     (((ks * 2 + khA) ^ swA) * 16));
                LDSM4(a[mf][0], a[mf][1], a[mf][2], a[mf][3], ad);
            }
            #pragma unroll
            for (int nfp = 0; nfp < 2; ++nfp) {
                const uint32_t bd = bb + (uint32_t)((rB + nfp * 16) * 64 +
                                     (((ks * 2 + khB) ^ swB) * 16));
                LDSM4(b[nfp * 2][0], b[nfp * 2][1], b[nfp * 2 + 1][0], b[nfp * 2 + 1][1], bd);
            }
            #pragma unroll
            for (int mf = 0; mf < 4; ++mf)
                #pragma unroll
                for (int nf = 0; nf < 4; ++nf)
                    mma16816(acc[mf][nf], a[mf], b[nf]);
        }
    }

    // Epilogue: registers -> gmem with alpha/bias
    const long rowBase = (long)(blockIdx.z * rowsA + blockIdx.y * 128) + wm * 64;
    const int  colBase = blockIdx.x * 128 + wn * 32;
    #pragma unroll
    for (int mf = 0; mf < 4; ++mf) {
        const long r0 = rowBase + mf * 16 + (lane >> 2);
        #pragma unroll
        for (int nf = 0; nf < 4; ++nf) {
            const int cc = colBase + nf * 8 + (lane & 3) * 2;
            float2 bv = make_float2(0.0f, 0.0f);
            if (bias) bv = *(const float2*)(bias + cc);
            float2 v0 = make_float2(acc[mf][nf][0] * alpha + bv.x,
                                    acc[mf][nf][1] * alpha + bv.y);
            float2 v1 = make_float2(acc[mf][nf][2] * alpha + bv.x,
                                    acc[mf][nf][3] * alpha + bv.y);
            *(float2*)(out + r0 * N + cc)       = v0;
            *(float2*)(out + (r0 + 8) * N + cc) = v1;
        }
    }
}

// ---------------- fp32 -> split-3 bf16 (PAT 0: A=[hi|lo|hi], PAT 1: B=[hi|hi|lo]) --------
template <int PAT>
__global__ __launch_bounds__(256) void conv_kernel(
    const float* __restrict__ in, __nv_bfloat16* __restrict__ out, int C, long total4)
{
    const long t = blockIdx.x * 256L + threadIdx.x;
    if (t >= total4) return;
    const long i = t * 4;
    const long r = i / C;
    const int  c = (int)(i - r * C);
    float4 v = *(const float4*)(in + i);
    float vv[4] = {v.x, v.y, v.z, v.w};
    union { __nv_bfloat16 b[4]; uint2 u; } H, L;
    #pragma unroll
    for (int j = 0; j < 4; ++j) {
        H.b[j] = __float2bfloat16(vv[j]);
        L.b[j] = __float2bfloat16(vv[j] - __bfloat162float(H.b[j]));
    }
    const long base = r * (3L * C) + c;
    *(uint2*)(out + base) = H.u;
    if (PAT == 0) {
        *(uint2*)(out + base + C)      = L.u;
        *(uint2*)(out + base + 2L * C) = H.u;
    } else {
        *(uint2*)(out + base + C)      = H.u;
        *(uint2*)(out + base + 2L * C) = L.u;
    }
}

// V [NB,S,A] fp32 -> Vt'' [NB, A, 3S] bf16 (B pattern)
__global__ void __launch_bounds__(1024) convT_kernel(
    const float* __restrict__ V, __nv_bfloat16* __restrict__ Vt)
{
    __shared__ float t[32][33];
    const int b  = blockIdx.z;
    const int s0 = blockIdx.y * 32, a0 = blockIdx.x * 32;
    const int x = threadIdx.x, y = threadIdx.y;
    t[y][x] = V[((long)b * SS + s0 + y) * AA + a0 + x];
    __syncthreads();
    const float v = t[x][y];
    const __nv_bfloat16 hi = __float2bfloat16(v);
    const __nv_bfloat16 lo = __float2bfloat16(v - __bfloat162float(hi));
    const long base = ((long)b * AA + a0 + y) * (long)K3S + (s0 + x);
    Vt[base]           = hi;
    Vt[base + SS]      = hi;
    Vt[base + 2L * SS] = lo;
}

// ---------------- softmax ----------------
__global__ __launch_bounds__(256) void softmax_rows_kernel(float* __restrict__ P, int n)
{
    float* p = P + (long)blockIdx.x * n;
    const int tid = threadIdx.x;
    __shared__ float red[256];
    float mx = -1e30f;
    for (int i = tid; i < n; i += 256) mx = fmaxf(mx, p[i]);
    red[tid] = mx; __syncthreads();
    #pragma unroll
    for (int s = 128; s > 0; s >>= 1) {
        if (tid < s) red[tid] = fmaxf(red[tid], red[tid + s]);
        __syncthreads();
    }
    mx = red[0]; __syncthreads();
    float sum = 0.0f;
    for (int i = tid; i < n; i += 256) {
        float e = __expf(p[i] - mx);
        p[i] = e; sum += e;
    }
    red[tid] = sum; __syncthreads();
    #pragma unroll
    for (int s = 128; s > 0; s >>= 1) {
        if (tid < s) red[tid] += red[tid + s];
        __syncthreads();
    }
    const float inv = 1.0f / red[0];
    for (int i = tid; i < n; i += 256) p[i] *= inv;
}

// ---------------- host ----------------
extern "C" void kernel_launch(void* const* d_in, const int* in_sizes, int n_in,
                              void* d_out, int out_size)
{
    const float* x  = (const float*)d_in[0];
    const float* Wq = (const float*)d_in[1];
    const float* bq = (const float*)d_in[2];
    const float* Wk = (const float*)d_in[3];
    const float* bk = (const float*)d_in[4];
    const float* Wv = (const float*)d_in[5];
    const float* bv = (const float*)d_in[6];
    const float* Wo = (const float*)d_in[7];
    const float* bo = (const float*)d_in[8];
    float* out = (float*)d_out;

    float *Q, *K, *V, *P, *C;
    __nv_bfloat16 *xA, *QA, *KB, *CA, *PA, *VT, *WqB, *WkB, *WvB, *WoB;
    cudaGetSymbolAddress((void**)&Q, g_Q);
    cudaGetSymbolAddress((void**)&K, g_K);
    cudaGetSymbolAddress((void**)&V, g_V);
    cudaGetSymbolAddress((void**)&P, g_P);
    cudaGetSymbolAddress((void**)&C, g_C);
    cudaGetSymbolAddress((void**)&xA, g_xA);
    cudaGetSymbolAddress((void**)&QA, g_QA);
    cudaGetSymbolAddress((void**)&KB, g_KB);
    cudaGetSymbolAddress((void**)&CA, g_CA);
    cudaGetSymbolAddress((void**)&PA, g_PA);
    cudaGetSymbolAddress((void**)&VT, g_VT);
    cudaGetSymbolAddress((void**)&WqB, g_WqB);
    cudaGetSymbolAddress((void**)&WkB, g_WkB);
    cudaGetSymbolAddress((void**)&WvB, g_WvB);
    cudaGetSymbolAddress((void**)&WoB, g_WoB);

    cudaFuncSetAttribute(mma_gemm_kernel,
                         cudaFuncAttributeMaxDynamicSharedMemorySize, GEMM_SMEM);

    const float scale = 0.03125f;  // 1/sqrt(1024)

    // split inputs
    long t4 = (long)NTOK * DD / 4;
    conv_kernel<0><<<(unsigned)((t4 + 255) / 256), 256>>>(x, xA, DD, t4);
    long w4 = (long)AA * DD / 4;
    conv_kernel<1><<<(unsigned)((w4 + 255) / 256), 256>>>(Wq, WqB, DD, w4);
    conv_kernel<1><<<(unsigned)((w4 + 255) / 256), 256>>>(Wk, WkB, DD, w4);
    conv_kernel<1><<<(unsigned)((w4 + 255) / 256), 256>>>(Wv, WvB, DD, w4);
    conv_kernel<1><<<(unsigned)((w4 + 255) / 256), 256>>>(Wo, WoB, AA, w4);

    // projections: [NTOK,3072] x [1024,3072]^T
    dim3 gproj(AA / 128, NTOK / 128, 1);
    mma_gemm_kernel<<<gproj, 256, GEMM_SMEM>>>(xA, WqB, bq, Q, AA, K3P, 1.0f, NTOK, AA);
    mma_gemm_kernel<<<gproj, 256, GEMM_SMEM>>>(xA, WkB, bk, K, AA, K3P, 1.0f, NTOK, AA);
    mma_gemm_kernel<<<gproj, 256, GEMM_SMEM>>>(xA, WvB, bv, V, AA, K3P, 1.0f, NTOK, AA);

    // re-split Q, K; transpose-split V
    long q4 = (long)NTOK * AA / 4;
    conv_kernel<0><<<(unsigned)((q4 + 255) / 256), 256>>>(Q, QA, AA, q4);
    conv_kernel<1><<<(unsigned)((q4 + 255) / 256), 256>>>(K, KB, AA, q4);
    convT_kernel<<<dim3(AA / 32, SS / 32, NB), dim3(32, 32)>>>(V, VT);

    // scores: per-batch [4096,3072] x [4096,3072]^T * scale
    dim3 gsc(SS / 128, SS / 128, NB);
    mma_gemm_kernel<<<gsc, 256, GEMM_SMEM>>>(QA, KB, nullptr, P, SS, K3P, scale, SS, SS);

    softmax_rows_kernel<<<NB * SS, 256>>>(P, SS);

    // split attn probs
    long p4 = (long)NTOK * SS / 4;
    conv_kernel<0><<<(unsigned)((p4 + 255) / 256), 256>>>(P, PA, SS, p4);

    // ctx: per-batch [4096,12288] x [1024,12288]^T
    dim3 gctx(AA / 128, SS / 128, NB);
    mma_gemm_kernel<<<gctx, 256, GEMM_SMEM>>>(PA, VT, nullptr, C, AA, K3S, 1.0f, SS, AA);

    // output projection
    long c4 = (long)NTOK * AA / 4;
    conv_kernel<0><<<(unsigned)((c4 + 255) / 256), 256>>>(C, CA, AA, c4);
    mma_gemm_kernel<<<gproj, 256, GEMM_SMEM>>>(CA, WoB, bo, out, DD, K3P, 1.0f, NTOK, DD);
}

// round 9
// speedup vs baseline: 1.3393x; 1.3393x over previous
#include <cuda_runtime.h>
#include <cuda_bf16.h>
#include <stdint.h>

#define NB   4
#define SS   4096
#define DD   1024
#define AA   1024
#define NTOK (NB * SS)
#define K3P  (3 * DD)
#define K3S  (3 * SS)

// Scratch (device globals: allocation-free rule)
__device__ float g_V[(size_t)NTOK * AA];
__device__ float g_P[(size_t)NB * SS * SS];
__device__ __nv_bfloat16 g_xA[(size_t)NTOK * K3P];
__device__ __nv_bfloat16 g_QA[(size_t)NTOK * K3P];
__device__ __nv_bfloat16 g_KB[(size_t)NTOK * K3P];
__device__ __nv_bfloat16 g_CA[(size_t)NTOK * K3P];
__device__ __nv_bfloat16 g_PA[(size_t)NTOK * (size_t)K3S];
__device__ __nv_bfloat16 g_VT[(size_t)NB * AA * (size_t)K3S];
__device__ __nv_bfloat16 g_WqB[(size_t)AA * K3P];
__device__ __nv_bfloat16 g_WkB[(size_t)AA * K3P];
__device__ __nv_bfloat16 g_WvB[(size_t)AA * K3P];
__device__ __nv_bfloat16 g_WoB[(size_t)DD * K3P];

// ---------------- PTX helpers (sm_103 baseline: no tcgen05/TMA) ----------
__device__ __forceinline__ uint32_t smem_u32(const void* p) {
    uint32_t a;
    asm("{ .reg .u64 t; cvta.to.shared.u64 t, %1; cvt.u32.u64 %0, t; }" : "=r"(a) : "l"(p));
    return a;
}
__device__ __forceinline__ void cp16(uint32_t dst, const void* src) {
    asm volatile("cp.async.cg.shared.global [%0], [%1], 16;" :: "r"(dst), "l"(src));
}
#define CP_COMMIT() asm volatile("cp.async.commit_group;" ::: "memory")
#define CP_WAIT2()  asm volatile("cp.async.wait_group 2;" ::: "memory")

#define LDSM4(R0, R1, R2, R3, ADDR) \
    asm volatile("ldmatrix.sync.aligned.m8n8.x4.shared.b16 {%0,%1,%2,%3}, [%4];" \
                 : "=r"(R0), "=r"(R1), "=r"(R2), "=r"(R3) : "r"(ADDR))

__device__ __forceinline__ void mma16816(float* d, const uint32_t* a, const uint32_t* b) {
    asm volatile(
        "mma.sync.aligned.m16n8k16.row.col.f32.bf16.bf16.f32 "
        "{%0,%1,%2,%3}, {%4,%5,%6,%7}, {%8,%9}, {%0,%1,%2,%3};"
        : "+f"(d[0]), "+f"(d[1]), "+f"(d[2]), "+f"(d[3])
        : "r"(a[0]), "r"(a[1]), "r"(a[2]), "r"(a[3]), "r"(b[0]), "r"(b[1]));
}

// ---------------------------------------------------------------------------
// GEMM: out[M,N] = alpha * A''[M,K3](bf16) * B''[N,K3](bf16)^T + bias
// BM=BN=128, BK=32, 8 warps (2x4), 4-stage cp.async, ONE syncthreads/iter.
// MODE 0: fp32 out[M,N]
// MODE 1: bf16 split-A out[M,3N] = [hi | lo | hi]
// MODE 2: bf16 split-B out[M,3N] = [hi | hi | lo]
// ---------------------------------------------------------------------------
#define BK 32
#define NSTAGE 4
#define STG_BYTES 16384            // A 8KB + B 8KB
#define GEMM_SMEM (NSTAGE * STG_BYTES)  // 65536

template <int MODE>
__global__ void __launch_bounds__(256, 2) mma_gemm_kernel(
    const __nv_bfloat16* __restrict__ A, const __nv_bfloat16* __restrict__ B,
    const float* __restrict__ bias, void* __restrict__ outv,
    int N, int K3, float alpha, int rowsA, int rowsB)
{
    extern __shared__ __align__(128) char smem[];
    const uint32_t sb = smem_u32(smem);
    const int tid  = threadIdx.x;
    const int lane = tid & 31;
    const int wid  = tid >> 5;
    const int wm   = wid >> 2;       // 0..1
    const int wn   = wid & 3;        // 0..3

    const int aRow = blockIdx.z * rowsA + blockIdx.y * 128;
    const int bRow = blockIdx.z * rowsB + blockIdx.x * 128;

    // cp.async loader: 2 A-chunks + 2 B-chunks of 16B per thread
    const int lr0 = tid >> 2;            // 0..63
    const int lr1 = lr0 + 64;
    const int lc  = tid & 3;
    const int sw0 = (lr0 >> 1) & 3;
    const uint32_t dA0 = (uint32_t)(lr0 * 64 + ((lc ^ sw0) * 16));
    const uint32_t dA1 = (uint32_t)(lr1 * 64 + ((lc ^ sw0) * 16));
    const __nv_bfloat16* gA0 = A + (long)(aRow + lr0) * K3 + lc * 8;
    const __nv_bfloat16* gA1 = A + (long)(aRow + lr1) * K3 + lc * 8;
    const __nv_bfloat16* gB0 = B + (long)(bRow + lr0) * K3 + lc * 8;
    const __nv_bfloat16* gB1 = B + (long)(bRow + lr1) * K3 + lc * 8;

    // ldmatrix lane addressing
    const int rA  = wm * 64 + (lane & 15);
    const int khA = lane >> 4;
    const int swA = (rA >> 1) & 3;
    const int rB  = wn * 32 + (lane & 7) + ((lane >> 4) << 3);
    const int khB = (lane >> 3) & 1;
    const int swB = (rB >> 1) & 3;

    float acc[4][4][4];
    #pragma unroll
    for (int i = 0; i < 4; ++i)
        #pragma unroll
        for (int j = 0; j < 4; ++j)
            #pragma unroll
            for (int e = 0; e < 4; ++e) acc[i][j][e] = 0.0f;

    const int NT = K3 / BK;

    // prologue: stages 0..2
    #pragma unroll
    for (int s = 0; s < NSTAGE - 1; ++s) {
        const uint32_t ab = sb + s * STG_BYTES;
        const long go = (long)s * BK;
        cp16(ab + dA0,        gA0 + go);
        cp16(ab + dA1,        gA1 + go);
        cp16(ab + 8192 + dA0, gB0 + go);
        cp16(ab + 8192 + dA1, gB1 + go);
        CP_COMMIT();
    }

    for (int kt = 0; kt < NT; ++kt) {
        CP_WAIT2();            // stage kt resident
        __syncthreads();       // all warps done reading buffer (kt-1)%4 as well

        if (kt + NSTAGE - 1 < NT) {
            const int s = (kt + NSTAGE - 1) % NSTAGE;
            const uint32_t ab = sb + s * STG_BYTES;
            const long go = (long)(kt + NSTAGE - 1) * BK;
            cp16(ab + dA0,        gA0 + go);
            cp16(ab + dA1,        gA1 + go);
            cp16(ab + 8192 + dA0, gB0 + go);
            cp16(ab + 8192 + dA1, gB1 + go);
        }
        CP_COMMIT();

        const uint32_t ab = sb + (kt % NSTAGE) * STG_BYTES;
        const uint32_t bb = ab + 8192;

        #pragma unroll
        for (int ks = 0; ks < 2; ++ks) {
            uint32_t a[4][4], b[4][2];
            #pragma unroll
            for (int mf = 0; mf < 4; ++mf) {
                const uint32_t ad = ab + (uint32_t)((rA + mf * 16) * 64 +
                                     (((ks * 2 + khA) ^ swA) * 16));
                LDSM4(a[mf][0], a[mf][1], a[mf][2], a[mf][3], ad);
            }
            #pragma unroll
            for (int nfp = 0; nfp < 2; ++nfp) {
                const uint32_t bd = bb + (uint32_t)((rB + nfp * 16) * 64 +
                                     (((ks * 2 + khB) ^ swB) * 16));
                LDSM4(b[nfp * 2][0], b[nfp * 2][1], b[nfp * 2 + 1][0], b[nfp * 2 + 1][1], bd);
            }
            #pragma unroll
            for (int mf = 0; mf < 4; ++mf)
                #pragma unroll
                for (int nf = 0; nf < 4; ++nf)
                    mma16816(acc[mf][nf], a[mf], b[nf]);
        }
    }

    // Epilogue
    const long rBase   = (long)(blockIdx.z * rowsA + blockIdx.y * 128) + wm * 64;
    const int  colBase = blockIdx.x * 128 + wn * 32;

    if (MODE == 0) {
        float* out = (float*)outv;
        #pragma unroll
        for (int mf = 0; mf < 4; ++mf) {
            const long r0 = rBase + mf * 16 + (lane >> 2);
            #pragma unroll
            for (int nf = 0; nf < 4; ++nf) {
                const int cc = colBase + nf * 8 + (lane & 3) * 2;
                float2 bv = make_float2(0.0f, 0.0f);
                if (bias) bv = *(const float2*)(bias + cc);
                float2 v0 = make_float2(acc[mf][nf][0] * alpha + bv.x,
                                        acc[mf][nf][1] * alpha + bv.y);
                float2 v1 = make_float2(acc[mf][nf][2] * alpha + bv.x,
                                        acc[mf][nf][3] * alpha + bv.y);
                *(float2*)(out + r0 * N + cc)       = v0;
                *(float2*)(out + (r0 + 8) * N + cc) = v1;
            }
        }
    } else {
        __nv_bfloat16* ob = (__nv_bfloat16*)outv;
        const long ldo = 3L * N;
        #pragma unroll
        for (int mf = 0; mf < 4; ++mf) {
            const long r0 = rBase + mf * 16 + (lane >> 2);
            #pragma unroll
            for (int nf = 0; nf < 4; ++nf) {
                const int cc = colBase + nf * 8 + (lane & 3) * 2;
                float2 bv = make_float2(0.0f, 0.0f);
                if (bias) bv = *(const float2*)(bias + cc);
                #pragma unroll
                for (int h = 0; h < 2; ++h) {
                    const long rr = r0 + h * 8;
                    float vx = acc[mf][nf][h * 2 + 0] * alpha + bv.x;
                    float vy = acc[mf][nf][h * 2 + 1] * alpha + bv.y;
                    union { __nv_bfloat16 b[2]; uint32_t u; } H, L;
                    H.b[0] = __float2bfloat16(vx);
                    H.b[1] = __float2bfloat16(vy);
                    L.b[0] = __float2bfloat16(vx - __bfloat162float(H.b[0]));
                    L.b[1] = __float2bfloat16(vy - __bfloat162float(H.b[1]));
                    uint32_t* p0 = (uint32_t*)(ob + rr * ldo + cc);
                    *p0 = H.u;
                    *(uint32_t*)(ob + rr * ldo + N + cc)     = (MODE == 1) ? L.u : H.u;
                    *(uint32_t*)(ob + rr * ldo + 2L * N + cc) = (MODE == 1) ? H.u : L.u;
                }
            }
        }
    }
}

// ---------------- fp32 -> split-3 bf16 converters -------------------------
template <int PAT>
__global__ __launch_bounds__(256) void conv_kernel(
    const float* __restrict__ in, __nv_bfloat16* __restrict__ out, int C, long total4)
{
    const long t = blockIdx.x * 256L + threadIdx.x;
    if (t >= total4) return;
    const long i = t * 4;
    const long r = i / C;
    const int  c = (int)(i - r * C);
    float4 v = *(const float4*)(in + i);
    float vv[4] = {v.x, v.y, v.z, v.w};
    union { __nv_bfloat16 b[4]; uint2 u; } H, L;
    #pragma unroll
    for (int j = 0; j < 4; ++j) {
        H.b[j] = __float2bfloat16(vv[j]);
        L.b[j] = __float2bfloat16(vv[j] - __bfloat162float(H.b[j]));
    }
    const long base = r * (3L * C) + c;
    *(uint2*)(out + base) = H.u;
    if (PAT == 0) {
        *(uint2*)(out + base + C)      = L.u;
        *(uint2*)(out + base + 2L * C) = H.u;
    } else {
        *(uint2*)(out + base + C)      = H.u;
        *(uint2*)(out + base + 2L * C) = L.u;
    }
}

// V [NB,S,A] fp32 -> Vt'' [NB, A, 3S] bf16 (B pattern)
__global__ void __launch_bounds__(1024) convT_kernel(
    const float* __restrict__ V, __nv_bfloat16* __restrict__ Vt)
{
    __shared__ float t[32][33];
    const int b  = blockIdx.z;
    const int s0 = blockIdx.y * 32, a0 = blockIdx.x * 32;
    const int x = threadIdx.x, y = threadIdx.y;
    t[y][x] = V[((long)b * SS + s0 + y) * AA + a0 + x];
    __syncthreads();
    const float v = t[x][y];
    const __nv_bfloat16 hi = __float2bfloat16(v);
    const __nv_bfloat16 lo = __float2bfloat16(v - __bfloat162float(hi));
    const long base = ((long)b * AA + a0 + y) * (long)K3S + (s0 + x);
    Vt[base]           = hi;
    Vt[base + SS]      = hi;
    Vt[base + 2L * SS] = lo;
}

// ---------------- fused softmax + split-A (hi|lo|hi) ----------------------
// One block per row (SS=4096). Row cached in registers: 16 floats/thread.
__global__ __launch_bounds__(256) void softmax_split_kernel(
    const float* __restrict__ P, __nv_bfloat16* __restrict__ PA)
{
    const float* p = P + (long)blockIdx.x * SS;
    __nv_bfloat16* o = PA + (long)blockIdx.x * (3L * SS);
    const int tid = threadIdx.x, lane = tid & 31, wrp = tid >> 5;
    __shared__ float red[8];

    float v[16];
    #pragma unroll
    for (int j = 0; j < 4; ++j) {
        float4 t = *(const float4*)(p + j * 1024 + tid * 4);
        v[j * 4 + 0] = t.x; v[j * 4 + 1] = t.y; v[j * 4 + 2] = t.z; v[j * 4 + 3] = t.w;
    }

    float mx = v[0];
    #pragma unroll
    for (int i = 1; i < 16; ++i) mx = fmaxf(mx, v[i]);
    #pragma unroll
    for (int off = 16; off; off >>= 1) mx = fmaxf(mx, __shfl_xor_sync(~0u, mx, off));
    if (lane == 0) red[wrp] = mx;
    __syncthreads();
    mx = red[0];
    #pragma unroll
    for (int w = 1; w < 8; ++w) mx = fmaxf(mx, red[w]);
    __syncthreads();

    float sum = 0.0f;
    #pragma unroll
    for (int i = 0; i < 16; ++i) { v[i] = __expf(v[i] - mx); sum += v[i]; }
    #pragma unroll
    for (int off = 16; off; off >>= 1) sum += __shfl_xor_sync(~0u, sum, off);
    if (lane == 0) red[wrp] = sum;
    __syncthreads();
    sum = 0.0f;
    #pragma unroll
    for (int w = 0; w < 8; ++w) sum += red[w];
    const float inv = 1.0f / sum;

    #pragma unroll
    for (int j = 0; j < 4; ++j) {
        const int col = j * 1024 + tid * 4;
        #pragma unroll
        for (int q = 0; q < 2; ++q) {
            float ax = v[j * 4 + q * 2 + 0] * inv;
            float ay = v[j * 4 + q * 2 + 1] * inv;
            union { __nv_bfloat16 b[2]; uint32_t u; } H, L;
            H.b[0] = __float2bfloat16(ax);
            H.b[1] = __float2bfloat16(ay);
            L.b[0] = __float2bfloat16(ax - __bfloat162float(H.b[0]));
            L.b[1] = __float2bfloat16(ay - __bfloat162float(H.b[1]));
            *(uint32_t*)(o + col + q * 2)            = H.u;
            *(uint32_t*)(o + SS + col + q * 2)       = L.u;
            *(uint32_t*)(o + 2L * SS + col + q * 2)  = H.u;
        }
    }
}

// ---------------- host ----------------
extern "C" void kernel_launch(void* const* d_in, const int* in_sizes, int n_in,
                              void* d_out, int out_size)
{
    const float* x  = (const float*)d_in[0];
    const float* Wq = (const float*)d_in[1];
    const float* bq = (const float*)d_in[2];
    const float* Wk = (const float*)d_in[3];
    const float* bk = (const float*)d_in[4];
    const float* Wv = (const float*)d_in[5];
    const float* bv = (const float*)d_in[6];
    const float* Wo = (const float*)d_in[7];
    const float* bo = (const float*)d_in[8];
    float* out = (float*)d_out;

    float *V, *P;
    __nv_bfloat16 *xA, *QA, *KB, *CA, *PA, *VT, *WqB, *WkB, *WvB, *WoB;
    cudaGetSymbolAddress((void**)&V, g_V);
    cudaGetSymbolAddress((void**)&P, g_P);
    cudaGetSymbolAddress((void**)&xA, g_xA);
    cudaGetSymbolAddress((void**)&QA, g_QA);
    cudaGetSymbolAddress((void**)&KB, g_KB);
    cudaGetSymbolAddress((void**)&CA, g_CA);
    cudaGetSymbolAddress((void**)&PA, g_PA);
    cudaGetSymbolAddress((void**)&VT, g_VT);
    cudaGetSymbolAddress((void**)&WqB, g_WqB);
    cudaGetSymbolAddress((void**)&WkB, g_WkB);
    cudaGetSymbolAddress((void**)&WvB, g_WvB);
    cudaGetSymbolAddress((void**)&WoB, g_WoB);

    cudaFuncSetAttribute(mma_gemm_kernel<0>,
                         cudaFuncAttributeMaxDynamicSharedMemorySize, GEMM_SMEM);
    cudaFuncSetAttribute(mma_gemm_kernel<1>,
                         cudaFuncAttributeMaxDynamicSharedMemorySize, GEMM_SMEM);
    cudaFuncSetAttribute(mma_gemm_kernel<2>,
                         cudaFuncAttributeMaxDynamicSharedMemorySize, GEMM_SMEM);

    const float scale = 0.03125f;  // 1/sqrt(1024)

    // split inputs (x + weights only — Q/K/ctx splits are fused in GEMM epilogues)
    long t4 = (long)NTOK * DD / 4;
    conv_kernel<0><<<(unsigned)((t4 + 255) / 256), 256>>>(x, xA, DD, t4);
    long w4 = (long)AA * DD / 4;
    conv_kernel<1><<<(unsigned)((w4 + 255) / 256), 256>>>(Wq, WqB, DD, w4);
    conv_kernel<1><<<(unsigned)((w4 + 255) / 256), 256>>>(Wk, WkB, DD, w4);
    conv_kernel<1><<<(unsigned)((w4 + 255) / 256), 256>>>(Wv, WvB, DD, w4);
    conv_kernel<1><<<(unsigned)((w4 + 255) / 256), 256>>>(Wo, WoB, AA, w4);

    // projections: Q -> split-A, K -> split-B, V -> fp32 (needs transpose)
    dim3 gproj(AA / 128, NTOK / 128, 1);
    mma_gemm_kernel<1><<<gproj, 256, GEMM_SMEM>>>(xA, WqB, bq, QA, AA, K3P, 1.0f, NTOK, AA);
    mma_gemm_kernel<2><<<gproj, 256, GEMM_SMEM>>>(xA, WkB, bk, KB, AA, K3P, 1.0f, NTOK, AA);
    mma_gemm_kernel<0><<<gproj, 256, GEMM_SMEM>>>(xA, WvB, bv, V,  AA, K3P, 1.0f, NTOK, AA);

    convT_kernel<<<dim3(AA / 32, SS / 32, NB), dim3(32, 32)>>>(V, VT);

    // scores: per-batch [4096,3072] x [4096,3072]^T * scale -> fp32 P
    dim3 gsc(SS / 128, SS / 128, NB);
    mma_gemm_kernel<0><<<gsc, 256, GEMM_SMEM>>>(QA, KB, nullptr, P, SS, K3P, scale, SS, SS);

    // fused softmax + split-A -> PA
    softmax_split_kernel<<<NB * SS, 256>>>(P, PA);

    // ctx: per-batch [4096,12288] x [1024,12288]^T -> split-A CA
    dim3 gctx(AA / 128, SS / 128, NB);
    mma_gemm_kernel<1><<<gctx, 256, GEMM_SMEM>>>(PA, VT, nullptr, CA, AA, K3S, 1.0f, SS, AA);

    // output projection -> fp32 out
    mma_gemm_kernel<0><<<gproj, 256, GEMM_SMEM>>>(CA, WoB, bo, out, DD, K3P, 1.0f, NTOK, DD);
}